// round 5
// baseline (speedup 1.0000x reference)
#include <cuda_runtime.h>
#include <cuda_bf16.h>
#include <cstdint>

#define BATCH 4
#define CDIM  256
#define NPIX  4096
typedef __nv_bfloat16 bf16;

#define CN ((size_t)BATCH * NPIX * CDIM)      // 4,194,304
#define NN ((size_t)BATCH * NPIX * NPIX)      // 67,108,864

// ---------------------------------------------------------------------------
// Device scratch
// ---------------------------------------------------------------------------
__device__ bf16  g_FcT_h[CN], g_FcT_l[CN];    // F_c transposed [b][p][c]
__device__ bf16  g_FsT_h[CN], g_FsT_l[CN];
__device__ bf16  g_wf_h[CDIM*CDIM], g_wf_l[CDIM*CDIM];
__device__ bf16  g_wg_h[CDIM*CDIM], g_wg_l[CDIM*CDIM];
__device__ bf16  g_wh_h[CDIM*CDIM], g_wh_l[CDIM*CDIM];
__device__ bf16  g_wo_h[CDIM*CDIM], g_wo_l[CDIM*CDIM];
__device__ bf16  g_Fq_h[CN], g_Fq_l[CN];      // [b][i][c]
__device__ bf16  g_G_h [CN], g_G_l [CN];      // [b][j][c]
__device__ bf16  g_Hv_h[CN], g_Hv_l[CN];      // [b][c][j]
__device__ bf16  g_R_h [CN], g_R_l [CN];      // [b][i][c]
__device__ float g_S[NN];                     // attention logits fp32
__device__ float g_stM[(size_t)BATCH * 32 * NPIX];   // per (z, jtile, i) tile max
__device__ float g_stS[(size_t)BATCH * 32 * NPIX];   // per (z, jtile, i) tile sumexp
__device__ float g_rowM[(size_t)BATCH * NPIX];       // final row max
__device__ float g_rowIL[(size_t)BATCH * NPIX];      // final 1/l

// ---------------------------------------------------------------------------
// PTX helpers (sm_80-level only)
// ---------------------------------------------------------------------------
__device__ __forceinline__ uint32_t smem_u32(const void* p) {
    uint32_t a;
    asm("{ .reg .u64 t; cvta.to.shared.u64 t, %1; cvt.u32.u64 %0, t; }" : "=r"(a) : "l"(p));
    return a;
}
#define CPA(s, g) asm volatile("cp.async.cg.shared.global [%0], [%1], 16;" :: "r"(s), "l"(g) : "memory")
#define CPC()     asm volatile("cp.async.commit_group;" ::: "memory")
#define CPW(n)    asm volatile("cp.async.wait_group %0;" :: "n"(n) : "memory")

__device__ __forceinline__ void ldsm4(uint32_t* r, uint32_t a) {
    asm volatile("ldmatrix.sync.aligned.m8n8.x4.shared.b16 {%0,%1,%2,%3}, [%4];"
        : "=r"(r[0]), "=r"(r[1]), "=r"(r[2]), "=r"(r[3]) : "r"(a));
}
__device__ __forceinline__ void ldsm2(uint32_t* r, uint32_t a) {
    asm volatile("ldmatrix.sync.aligned.m8n8.x2.shared.b16 {%0,%1}, [%2];"
        : "=r"(r[0]), "=r"(r[1]) : "r"(a));
}
__device__ __forceinline__ void mma_bf16(float* c, const uint32_t* a, const uint32_t* b) {
    asm volatile("mma.sync.aligned.m16n8k16.row.col.f32.bf16.bf16.f32 "
        "{%0,%1,%2,%3}, {%4,%5,%6,%7}, {%8,%9}, {%0,%1,%2,%3};"
        : "+f"(c[0]), "+f"(c[1]), "+f"(c[2]), "+f"(c[3])
        : "r"(a[0]), "r"(a[1]), "r"(a[2]), "r"(a[3]), "r"(b[0]), "r"(b[1]));
}
__device__ __forceinline__ void split2(float x, bf16& h, bf16& l) {
    h = __float2bfloat16(x);
    l = __float2bfloat16(x - __bfloat162float(h));
}

// ---------------------------------------------------------------------------
// GEMM: D[m,n] = sum_k A[m,k]*B[n,k]; K-contiguous bf16 hi/lo operands.
// CTA 128x128, BK=32, double-buffered cp.async, single sync per k-chunk,
// 8 warps (warp tile 64x32), 2 CTAs/SM. 3-pass hi/lo split.
// EPI:   0 = fp32 [m][n] (+bias), 1 = bf16 split [m][n] (+bias),
//        2 = bf16 split transposed [n][m] (+bias on m)
// STATS: epilogue also emits per-(row, n-tile) max & sumexp  (G4)
// FUSEB: B operand built on the fly as exp(S - m)*invl, split hi/lo (G5)
// ---------------------------------------------------------------------------
#define RSB      80
#define TILE_SB  (128 * RSB)     // 10240
#define STAGE_SB (4 * TILE_SB)   // 40960
#define DSMEM    (2 * STAGE_SB)  // 81920

template <int EPI, bool STATS, bool FUSEB>
__global__ void __launch_bounds__(256, 2)
mma_gemm(const bf16* __restrict__ Ah_, const bf16* __restrict__ Al_,
         const bf16* __restrict__ Bh_, const bf16* __restrict__ Bl_,
         int K, int lda, int ldb, int ldo,
         long long sA, long long sB, long long sO,
         const float* __restrict__ bias,
         float* __restrict__ outF, bf16* __restrict__ oH, bf16* __restrict__ oL,
         const float* __restrict__ Sfp, const float* __restrict__ rowM,
         const float* __restrict__ rowIL,
         float* __restrict__ stM, float* __restrict__ stS)
{
    extern __shared__ char smem[];
    const uint32_t sb = smem_u32(smem);
    const int tid = threadIdx.x;
    const int lane = tid & 31, wid = tid >> 5;
    const int wm = wid >> 2, wn = wid & 3;        // 2 x 4 warp grid
    const int z = blockIdx.z;
    const int m0 = blockIdx.y * 128, n0 = blockIdx.x * 128;

    const bf16* pT[4] = {Ah_ + (size_t)z * sA, Al_ + (size_t)z * sA,
                         Bh_ + (size_t)z * sB, Bl_ + (size_t)z * sB};
    const int nk = K / 32;

    const int r0 = tid >> 2, c0 = tid & 3;        // 16B chunk coords (rows 0..63)
    const int r1 = r0 + 64;
    const int ntile = FUSEB ? 2 : 4;

    auto issue = [&](int kc) {
        if (kc >= nk) return;
        const uint32_t s0 = sb + (kc & 1) * STAGE_SB;
#pragma unroll
        for (int t = 0; t < 4; ++t) {
            if (t >= ntile) break;
            const int ld = (t < 2) ? lda : ldb;
            const int base = (t < 2) ? m0 : n0;
            const bf16* g0 = pT[t] + (size_t)(base + r0) * ld + kc * 32 + c0 * 8;
            const bf16* g1 = pT[t] + (size_t)(base + r1) * ld + kc * 32 + c0 * 8;
            CPA(s0 + t * TILE_SB + r0 * RSB + c0 * 16, g0);
            CPA(s0 + t * TILE_SB + r1 * RSB + c0 * 16, g1);
        }
    };

    // FUSEB state: thread owns one B-row (pr) and half its 32 k-cols
    const int pr = tid >> 1, jh = tid & 1;
    float fb[16];
    float mrow = 0.f, il = 0.f;
    const float* Srow = nullptr;
    if (FUSEB) {
        Srow = Sfp + (size_t)z * NN / BATCH * 0;   // placeholder; real below
        Srow = Sfp + (size_t)z * (size_t)NPIX * NPIX + (size_t)(n0 + pr) * NPIX;
        mrow = rowM [(size_t)z * NPIX + n0 + pr];
        il   = rowIL[(size_t)z * NPIX + n0 + pr];
    }
    auto ldgB = [&](int kc) {
        if (kc >= nk) return;
        const float4* p = (const float4*)(Srow + kc * 32 + jh * 16);
#pragma unroll
        for (int q = 0; q < 4; ++q) {
            float4 v = p[q];
            fb[q*4] = v.x; fb[q*4+1] = v.y; fb[q*4+2] = v.z; fb[q*4+3] = v.w;
        }
    };
    auto stsB = [&](int kc) {
        const uint32_t s0 = sb + (kc & 1) * STAGE_SB;
        uint32_t hw[8], lw[8];
#pragma unroll
        for (int q = 0; q < 8; ++q) {
            float p0 = __expf(fb[q*2]   - mrow) * il;
            float p1 = __expf(fb[q*2+1] - mrow) * il;
            bf16 h0, l0, h1, l1;
            split2(p0, h0, l0); split2(p1, h1, l1);
            __nv_bfloat162 hp(h0, h1), lp(l0, l1);
            hw[q] = *(uint32_t*)&hp; lw[q] = *(uint32_t*)&lp;
        }
        const uint32_t dH = s0 + 2 * TILE_SB + pr * RSB + jh * 32;
        const uint32_t dL = s0 + 3 * TILE_SB + pr * RSB + jh * 32;
        asm volatile("st.shared.v4.b32 [%0], {%1,%2,%3,%4};" :: "r"(dH), "r"(hw[0]), "r"(hw[1]), "r"(hw[2]), "r"(hw[3]) : "memory");
        asm volatile("st.shared.v4.b32 [%0], {%1,%2,%3,%4};" :: "r"(dH+16), "r"(hw[4]), "r"(hw[5]), "r"(hw[6]), "r"(hw[7]) : "memory");
        asm volatile("st.shared.v4.b32 [%0], {%1,%2,%3,%4};" :: "r"(dL), "r"(lw[0]), "r"(lw[1]), "r"(lw[2]), "r"(lw[3]) : "memory");
        asm volatile("st.shared.v4.b32 [%0], {%1,%2,%3,%4};" :: "r"(dL+16), "r"(lw[4]), "r"(lw[5]), "r"(lw[6]), "r"(lw[7]) : "memory");
    };

    float acc[4][4][4];
#pragma unroll
    for (int i = 0; i < 4; ++i)
#pragma unroll
        for (int j = 0; j < 4; ++j)
#pragma unroll
            for (int q = 0; q < 4; ++q) acc[i][j][q] = 0.f;

    issue(0); CPC();
    if (FUSEB) ldgB(0);

    const int aRow = lane & 15;
    const int aKB  = (lane >> 4) * 16;
    const int bRow = lane & 7;
    const int bKB  = ((lane >> 3) & 1) * 16;

    for (int kc = 0; kc < nk; ++kc) {
        CPW(0);
        if (FUSEB) stsB(kc);
        __syncthreads();
        issue(kc + 1); CPC();
        if (FUSEB) ldgB(kc + 1);

        const uint32_t s0 = sb + (kc & 1) * STAGE_SB;
        const uint32_t aH = s0, aL = s0 + TILE_SB;
        const uint32_t bH = s0 + 2 * TILE_SB, bL = s0 + 3 * TILE_SB;
#pragma unroll
        for (int ks = 0; ks < 2; ++ks) {
            uint32_t Af[2][4][4];
#pragma unroll
            for (int i = 0; i < 4; ++i) {
                const uint32_t off = (uint32_t)(wm * 64 + i * 16 + aRow) * RSB + ks * 32 + aKB;
                ldsm4(Af[0][i], aH + off);
                ldsm4(Af[1][i], aL + off);
            }
#pragma unroll
            for (int j = 0; j < 4; ++j) {
                uint32_t Bf[2][2];
                const uint32_t off = (uint32_t)(wn * 32 + j * 8 + bRow) * RSB + ks * 32 + bKB;
                ldsm2(Bf[0], bH + off);
                ldsm2(Bf[1], bL + off);
#pragma unroll
                for (int i = 0; i < 4; ++i) {
                    mma_bf16(acc[i][j], Af[0][i], Bf[0]);   // hi*hi
                    mma_bf16(acc[i][j], Af[0][i], Bf[1]);   // hi*lo
                    mma_bf16(acc[i][j], Af[1][i], Bf[0]);   // lo*hi
                }
            }
        }
        __syncthreads();   // safe stage reuse next iter + stg overwrite after loop
    }

    // ---- epilogue: stage D (+bias on m) through smem ----
    float* stg = (float*)smem;                   // [128][132] = 67.6KB
    const int gid = lane >> 2, tig = lane & 3;
#pragma unroll
    for (int i = 0; i < 4; ++i) {
        const int ml = wm * 64 + i * 16 + gid;
        const float bv0 = bias ? bias[m0 + ml] : 0.f;
        const float bv8 = bias ? bias[m0 + ml + 8] : 0.f;
#pragma unroll
        for (int j = 0; j < 4; ++j) {
            const int nl = wn * 32 + j * 8 + tig * 2;
            stg[ml * 132 + nl]           = acc[i][j][0] + bv0;
            stg[ml * 132 + nl + 1]       = acc[i][j][1] + bv0;
            stg[(ml + 8) * 132 + nl]     = acc[i][j][2] + bv8;
            stg[(ml + 8) * 132 + nl + 1] = acc[i][j][3] + bv8;
        }
    }
    __syncthreads();

    const int row = tid >> 1, half = tid & 1;
    if (EPI == 0) {
        float* dst = outF + (size_t)z * sO + (size_t)(m0 + row) * ldo + n0 + half * 64;
        const float4* s4 = (const float4*)&stg[row * 132 + half * 64];
#pragma unroll
        for (int i = 0; i < 16; ++i) ((float4*)dst)[i] = s4[i];
    } else if (EPI == 1) {
        const size_t base = (size_t)z * sO + (size_t)(m0 + row) * ldo + n0 + half * 64;
#pragma unroll
        for (int v = 0; v < 8; ++v) {
            uint32_t hw[4], lw[4];
#pragma unroll
            for (int q = 0; q < 4; ++q) {
                float x0 = stg[row * 132 + half * 64 + v * 8 + q * 2];
                float x1 = stg[row * 132 + half * 64 + v * 8 + q * 2 + 1];
                bf16 h0, l0, h1, l1;
                split2(x0, h0, l0); split2(x1, h1, l1);
                __nv_bfloat162 hp(h0, h1), lp(l0, l1);
                hw[q] = *(uint32_t*)&hp; lw[q] = *(uint32_t*)&lp;
            }
            *(uint4*)(oH + base + v * 8) = make_uint4(hw[0], hw[1], hw[2], hw[3]);
            *(uint4*)(oL + base + v * 8) = make_uint4(lw[0], lw[1], lw[2], lw[3]);
        }
    } else {
        const int n = row, mh = half * 64;
        const size_t base = (size_t)z * sO + (size_t)(n0 + n) * ldo + m0 + mh;
#pragma unroll
        for (int v = 0; v < 8; ++v) {
            uint32_t hw[4], lw[4];
#pragma unroll
            for (int q = 0; q < 4; ++q) {
                float x0 = stg[(mh + v * 8 + q * 2) * 132 + n];
                float x1 = stg[(mh + v * 8 + q * 2 + 1) * 132 + n];
                bf16 h0, l0, h1, l1;
                split2(x0, h0, l0); split2(x1, h1, l1);
                __nv_bfloat162 hp(h0, h1), lp(l0, l1);
                hw[q] = *(uint32_t*)&hp; lw[q] = *(uint32_t*)&lp;
            }
            *(uint4*)(oH + base + v * 8) = make_uint4(hw[0], hw[1], hw[2], hw[3]);
            *(uint4*)(oL + base + v * 8) = make_uint4(lw[0], lw[1], lw[2], lw[3]);
        }
    }

    if (STATS) {
        // per-row (i = m0+row) stats over this n-tile's 128 cols
        float mx = -3.0e38f;
#pragma unroll
        for (int q = 0; q < 64; ++q) mx = fmaxf(mx, stg[row * 132 + half * 64 + q]);
        mx = fmaxf(mx, __shfl_xor_sync(0xffffffffu, mx, 1));
        float s = 0.f;
#pragma unroll
        for (int q = 0; q < 64; ++q) s += __expf(stg[row * 132 + half * 64 + q] - mx);
        s += __shfl_xor_sync(0xffffffffu, s, 1);
        if (half == 0) {
            size_t o = ((size_t)z * 32 + blockIdx.x) * NPIX + m0 + row;
            stM[o] = mx; stS[o] = s;
        }
    }
}

// ---------------------------------------------------------------------------
// Combine per-tile stats -> per-row (m, 1/l)
// ---------------------------------------------------------------------------
__global__ void __launch_bounds__(256)
combine_stats(const float* __restrict__ stM, const float* __restrict__ stS,
              float* __restrict__ rowM, float* __restrict__ rowIL)
{
    const int idx = blockIdx.x * 256 + threadIdx.x;          // z*4096 + i
    if (idx >= BATCH * NPIX) return;
    const int z = idx >> 12, i = idx & (NPIX - 1);
    float m = -3.0e38f;
#pragma unroll 4
    for (int t = 0; t < 32; ++t)
        m = fmaxf(m, stM[((size_t)z * 32 + t) * NPIX + i]);
    float l = 0.f;
#pragma unroll 4
    for (int t = 0; t < 32; ++t) {
        size_t o = ((size_t)z * 32 + t) * NPIX + i;
        l += stS[o] * __expf(stM[o] - m);
    }
    rowM[idx] = m;
    rowIL[idx] = 1.0f / l;
}

// ---------------------------------------------------------------------------
// Both inputs: fp32 [b][c][p] -> bf16 hi/lo transposed [b][p][c]  (one launch)
// ---------------------------------------------------------------------------
__global__ void __launch_bounds__(256)
tsplit_both(const float* __restrict__ Fc, const float* __restrict__ Fs,
            bf16* __restrict__ ohc, bf16* __restrict__ olc,
            bf16* __restrict__ ohs, bf16* __restrict__ ols)
{
    __shared__ float t[32][33];
    const int zz = blockIdx.z;
    const int b = zz & 3;
    const float* X = (zz < 4) ? Fc : Fs;
    bf16* oh = (zz < 4) ? ohc : ohs;
    bf16* ol = (zz < 4) ? olc : ols;
    const int pb = blockIdx.x * 32, cb = blockIdx.y * 32;
    const float* src = X + (size_t)b * CDIM * NPIX;
#pragma unroll
    for (int j = 0; j < 4; ++j) {
        int c = cb + threadIdx.y + j * 8;
        t[threadIdx.y + j * 8][threadIdx.x] = src[(size_t)c * NPIX + pb + threadIdx.x];
    }
    __syncthreads();
#pragma unroll
    for (int j = 0; j < 4; ++j) {
        int p = pb + threadIdx.y + j * 8;
        float v = t[threadIdx.x][threadIdx.y + j * 8];
        size_t o = (size_t)b * NPIX * CDIM + (size_t)p * CDIM + cb + threadIdx.x;
        bf16 h, l; split2(v, h, l);
        oh[o] = h; ol[o] = l;
    }
}

// All 4 weight matrices in one launch
__global__ void __launch_bounds__(256)
wsplit_all(const float* __restrict__ w0, const float* __restrict__ w1,
           const float* __restrict__ w2, const float* __restrict__ w3,
           bf16* __restrict__ h0, bf16* __restrict__ l0,
           bf16* __restrict__ h1, bf16* __restrict__ l1,
           bf16* __restrict__ h2, bf16* __restrict__ l2,
           bf16* __restrict__ h3, bf16* __restrict__ l3)
{
    const float* w = (blockIdx.y == 0) ? w0 : (blockIdx.y == 1) ? w1 : (blockIdx.y == 2) ? w2 : w3;
    bf16* hh = (blockIdx.y == 0) ? h0 : (blockIdx.y == 1) ? h1 : (blockIdx.y == 2) ? h2 : h3;
    bf16* ll = (blockIdx.y == 0) ? l0 : (blockIdx.y == 1) ? l1 : (blockIdx.y == 2) ? l2 : l3;
    int i = blockIdx.x * 256 + threadIdx.x;
    if (i < CDIM * CDIM) { bf16 a, b; split2(w[i], a, b); hh[i] = a; ll[i] = b; }
}

// ---------------------------------------------------------------------------
// Launch. Order: wsplit(1), tsplit_both(2), G1(3), G2(4), G4(5: ncu target),
//                G3(6), combine(7), G5(8), G6(9)
// ---------------------------------------------------------------------------
extern "C" void kernel_launch(void* const* d_in, const int* in_sizes, int n_in,
                              void* d_out, int out_size)
{
    const float* F_c = (const float*)d_in[0];
    const float* F_s = (const float*)d_in[1];
    const float* w_f = (const float*)d_in[2];
    const float* b_f = (const float*)d_in[3];
    const float* w_g = (const float*)d_in[4];
    const float* b_g = (const float*)d_in[5];
    const float* w_h = (const float*)d_in[6];
    const float* b_h = (const float*)d_in[7];
    const float* w_o = (const float*)d_in[8];
    const float* b_o = (const float*)d_in[9];
    float* out = (float*)d_out;

    bf16 *FcTh, *FcTl, *FsTh, *FsTl, *wfh, *wfl, *wgh, *wgl, *whh, *whl, *woh, *wol;
    bf16 *Fqh, *Fql, *Gh, *Gl, *Hvh, *Hvl, *Rh, *Rl;
    float *S, *stM, *stS, *rowM, *rowIL;
    cudaGetSymbolAddress((void**)&FcTh, g_FcT_h); cudaGetSymbolAddress((void**)&FcTl, g_FcT_l);
    cudaGetSymbolAddress((void**)&FsTh, g_FsT_h); cudaGetSymbolAddress((void**)&FsTl, g_FsT_l);
    cudaGetSymbolAddress((void**)&wfh, g_wf_h);   cudaGetSymbolAddress((void**)&wfl, g_wf_l);
    cudaGetSymbolAddress((void**)&wgh, g_wg_h);   cudaGetSymbolAddress((void**)&wgl, g_wg_l);
    cudaGetSymbolAddress((void**)&whh, g_wh_h);   cudaGetSymbolAddress((void**)&whl, g_wh_l);
    cudaGetSymbolAddress((void**)&woh, g_wo_h);   cudaGetSymbolAddress((void**)&wol, g_wo_l);
    cudaGetSymbolAddress((void**)&Fqh, g_Fq_h);   cudaGetSymbolAddress((void**)&Fql, g_Fq_l);
    cudaGetSymbolAddress((void**)&Gh,  g_G_h);    cudaGetSymbolAddress((void**)&Gl,  g_G_l);
    cudaGetSymbolAddress((void**)&Hvh, g_Hv_h);   cudaGetSymbolAddress((void**)&Hvl, g_Hv_l);
    cudaGetSymbolAddress((void**)&Rh,  g_R_h);    cudaGetSymbolAddress((void**)&Rl,  g_R_l);
    cudaGetSymbolAddress((void**)&S,   g_S);
    cudaGetSymbolAddress((void**)&stM, g_stM);    cudaGetSymbolAddress((void**)&stS, g_stS);
    cudaGetSymbolAddress((void**)&rowM, g_rowM);  cudaGetSymbolAddress((void**)&rowIL, g_rowIL);

    cudaFuncSetAttribute(mma_gemm<2,false,false>, cudaFuncAttributeMaxDynamicSharedMemorySize, DSMEM);
    cudaFuncSetAttribute(mma_gemm<1,false,false>, cudaFuncAttributeMaxDynamicSharedMemorySize, DSMEM);
    cudaFuncSetAttribute(mma_gemm<0,true ,false>, cudaFuncAttributeMaxDynamicSharedMemorySize, DSMEM);
    cudaFuncSetAttribute(mma_gemm<2,false,true >, cudaFuncAttributeMaxDynamicSharedMemorySize, DSMEM);
    cudaFuncSetAttribute(mma_gemm<0,false,false>, cudaFuncAttributeMaxDynamicSharedMemorySize, DSMEM);

    const long long cn = (long long)NPIX * CDIM;
    const long long nn = (long long)NPIX * NPIX;

    dim3 gConv(NPIX / 128, CDIM / 128, BATCH);   // 32 x 2 x 4
    dim3 gS(NPIX / 128, NPIX / 128, BATCH);      // 32 x 32 x 4

    // L1: weight splits
    wsplit_all<<<dim3(256, 4), 256>>>(w_f, w_g, w_h, w_o,
        wfh, wfl, wgh, wgl, whh, whl, woh, wol);
    // L2: both input transposes
    tsplit_both<<<dim3(128, 8, 8), dim3(32, 8)>>>(F_c, F_s, FcTh, FcTl, FsTh, FsTl);
    // L3 (G1): Fq_t[i][c]
    mma_gemm<2,false,false><<<gConv, 256, DSMEM>>>(wfh, wfl, FcTh, FcTl,
        CDIM, CDIM, CDIM, CDIM, 0, cn, cn, b_f, nullptr, Fqh, Fql,
        nullptr, nullptr, nullptr, nullptr, nullptr);
    // L4 (G2): G_t[j][c]
    mma_gemm<2,false,false><<<gConv, 256, DSMEM>>>(wgh, wgl, FsTh, FsTl,
        CDIM, CDIM, CDIM, CDIM, 0, cn, cn, b_g, nullptr, Gh, Gl,
        nullptr, nullptr, nullptr, nullptr, nullptr);
    // L5 (G4): S[i][j] + per-tile softmax stats  — ncu target
    mma_gemm<0,true,false><<<gS, 256, DSMEM>>>(Fqh, Fql, Gh, Gl,
        CDIM, CDIM, CDIM, NPIX, cn, cn, nn, nullptr, S, nullptr, nullptr,
        nullptr, nullptr, nullptr, stM, stS);
    // L6 (G3): Hv[c][j]
    mma_gemm<1,false,false><<<gConv, 256, DSMEM>>>(whh, whl, FsTh, FsTl,
        CDIM, CDIM, CDIM, NPIX, 0, cn, cn, b_h, nullptr, Hvh, Hvl,
        nullptr, nullptr, nullptr, nullptr, nullptr);
    // L7: fold stats -> (m, 1/l)
    combine_stats<<<(BATCH * NPIX + 255) / 256, 256>>>(stM, stS, rowM, rowIL);
    // L8 (G5): R_t[i][c], P built on the fly from fp32 S
    mma_gemm<2,false,true><<<gConv, 256, DSMEM>>>(Hvh, Hvl, nullptr, nullptr,
        NPIX, NPIX, NPIX, CDIM, cn, nn, cn, nullptr, nullptr, Rh, Rl,
        S, rowM, rowIL, nullptr, nullptr);
    // L9 (G6): out = w_o @ R + b_o
    mma_gemm<0,false,false><<<gConv, 256, DSMEM>>>(woh, wol, Rh, Rl,
        CDIM, CDIM, CDIM, NPIX, 0, cn, cn, b_o, out, nullptr, nullptr,
        nullptr, nullptr, nullptr, nullptr, nullptr);
}

// round 6
// speedup vs baseline: 1.0257x; 1.0257x over previous
#include <cuda_runtime.h>
#include <cuda_bf16.h>
#include <cstdint>

#define BATCH 4
#define CDIM  256
#define NPIX  4096
typedef __nv_bfloat16 bf16;

#define CN ((size_t)BATCH * NPIX * CDIM)      // 4,194,304
#define NN ((size_t)BATCH * NPIX * NPIX)      // 67,108,864

// ---------------------------------------------------------------------------
// Device scratch
// ---------------------------------------------------------------------------
__device__ bf16  g_FcT_h[CN], g_FcT_l[CN];    // F_c transposed [b][p][c]
__device__ bf16  g_FsT_h[CN], g_FsT_l[CN];
__device__ bf16  g_wf_h[CDIM*CDIM], g_wf_l[CDIM*CDIM];
__device__ bf16  g_wg_h[CDIM*CDIM], g_wg_l[CDIM*CDIM];
__device__ bf16  g_wh_h[CDIM*CDIM], g_wh_l[CDIM*CDIM];
__device__ bf16  g_wo_h[CDIM*CDIM], g_wo_l[CDIM*CDIM];
__device__ bf16  g_Fq_h[CN], g_Fq_l[CN];      // [b][i][c]
__device__ bf16  g_G_h [CN], g_G_l [CN];      // [b][j][c]
__device__ bf16  g_Hv_h[CN], g_Hv_l[CN];      // [b][c][j]
__device__ bf16  g_R_h [CN], g_R_l [CN];      // [b][i][c]
__device__ float g_S[NN];                     // attention logits fp32
__device__ float g_stM[(size_t)BATCH * 32 * NPIX];
__device__ float g_stS[(size_t)BATCH * 32 * NPIX];
__device__ float g_rowM[(size_t)BATCH * NPIX];
__device__ float g_rowIL[(size_t)BATCH * NPIX];

// ---------------------------------------------------------------------------
// PTX helpers (sm_80-level only)
// ---------------------------------------------------------------------------
__device__ __forceinline__ uint32_t smem_u32(const void* p) {
    uint32_t a;
    asm("{ .reg .u64 t; cvta.to.shared.u64 t, %1; cvt.u32.u64 %0, t; }" : "=r"(a) : "l"(p));
    return a;
}
#define CPA(s, g) asm volatile("cp.async.cg.shared.global [%0], [%1], 16;" :: "r"(s), "l"(g) : "memory")
#define CPC()     asm volatile("cp.async.commit_group;" ::: "memory")
#define CPW(n)    asm volatile("cp.async.wait_group %0;" :: "n"(n) : "memory")

__device__ __forceinline__ void ldsm4(uint32_t* r, uint32_t a) {
    asm volatile("ldmatrix.sync.aligned.m8n8.x4.shared.b16 {%0,%1,%2,%3}, [%4];"
        : "=r"(r[0]), "=r"(r[1]), "=r"(r[2]), "=r"(r[3]) : "r"(a));
}
__device__ __forceinline__ void ldsm2(uint32_t* r, uint32_t a) {
    asm volatile("ldmatrix.sync.aligned.m8n8.x2.shared.b16 {%0,%1}, [%2];"
        : "=r"(r[0]), "=r"(r[1]) : "r"(a));
}
__device__ __forceinline__ void mma_bf16(float* c, const uint32_t* a, const uint32_t* b) {
    asm volatile("mma.sync.aligned.m16n8k16.row.col.f32.bf16.bf16.f32 "
        "{%0,%1,%2,%3}, {%4,%5,%6,%7}, {%8,%9}, {%0,%1,%2,%3};"
        : "+f"(c[0]), "+f"(c[1]), "+f"(c[2]), "+f"(c[3])
        : "r"(a[0]), "r"(a[1]), "r"(a[2]), "r"(a[3]), "r"(b[0]), "r"(b[1]));
}
__device__ __forceinline__ void split2(float x, bf16& h, bf16& l) {
    h = __float2bfloat16(x);
    l = __float2bfloat16(x - __bfloat162float(h));
}

// ---------------------------------------------------------------------------
// GEMM: D[m,n] = sum_k A[m,k]*B[n,k]; K-contiguous bf16 hi/lo operands.
// CTA 128x128, BK=32, R4 double-buffered cp.async loop, 8 warps, 2 CTAs/SM.
// EPI:   0 = fp32 [m][n] (+bias), 1 = bf16 split [m][n], 2 = split transposed
// STATS: epilogue emits per-(row, n-tile) max & sumexp           (G4)
// FUSEB: B tile built in-kernel: fp32 S staged via cp.async into smem,
//        converted to exp(S-m)*il hi/lo splits (short-lived regs)  (G5)
// ---------------------------------------------------------------------------
#define RSB      80
#define TILE_SB  (128 * RSB)     // 10240
#define STAGE_SB (4 * TILE_SB)   // 40960
#define SF_ROW   144             // padded fp32 staging row (bytes)
#define SF_SB    (128 * SF_ROW)  // 18432
#define DSMEM    (2 * STAGE_SB)           // 81920 (non-FUSEB)
#define DSMEM_F  (2 * STAGE_SB + SF_SB)   // 100352 (FUSEB)

template <int EPI, bool STATS, bool FUSEB>
__global__ void __launch_bounds__(256, 2)
mma_gemm(const bf16* __restrict__ Ah_, const bf16* __restrict__ Al_,
         const bf16* __restrict__ Bh_, const bf16* __restrict__ Bl_,
         int K, int lda, int ldb, int ldo,
         long long sA, long long sB, long long sO,
         const float* __restrict__ bias,
         float* __restrict__ outF, bf16* __restrict__ oH, bf16* __restrict__ oL,
         const float* __restrict__ Sfp, const float* __restrict__ rowM,
         const float* __restrict__ rowIL,
         float* __restrict__ stM, float* __restrict__ stS)
{
    extern __shared__ char smem[];
    const uint32_t sb = smem_u32(smem);
    const int tid = threadIdx.x;
    const int lane = tid & 31, wid = tid >> 5;
    const int wm = wid >> 2, wn = wid & 3;        // 2 x 4 warp grid
    const int z = blockIdx.z;
    const int m0 = blockIdx.y * 128, n0 = blockIdx.x * 128;

    const bf16* pT[4] = {Ah_ + (size_t)z * sA, Al_ + (size_t)z * sA,
                         FUSEB ? nullptr : Bh_ + (size_t)z * sB,
                         FUSEB ? nullptr : Bl_ + (size_t)z * sB};
    const int nk = K / 32;

    const int r0 = tid >> 2, c0 = tid & 3;
    const int r1 = r0 + 64;

    auto issueA = [&](int kc) {   // A tiles always; B tiles only when !FUSEB
        if (kc >= nk) return;
        const uint32_t s0 = sb + (kc & 1) * STAGE_SB;
#pragma unroll
        for (int t = 0; t < (FUSEB ? 2 : 4); ++t) {
            const int ld = (t < 2) ? lda : ldb;
            const int base = (t < 2) ? m0 : n0;
            const bf16* g0 = pT[t] + (size_t)(base + r0) * ld + kc * 32 + c0 * 8;
            const bf16* g1 = pT[t] + (size_t)(base + r1) * ld + kc * 32 + c0 * 8;
            CPA(s0 + t * TILE_SB + r0 * RSB + c0 * 16, g0);
            CPA(s0 + t * TILE_SB + r1 * RSB + c0 * 16, g1);
        }
    };

    // FUSEB: per-thread row of the S tile
    const int pr = tid >> 1, jh = tid & 1;
    const uint32_t sf = sb + 2 * STAGE_SB;
    float mrow = 0.f, il = 0.f;
    const float* Srow = nullptr;
    if (FUSEB) {
        Srow = Sfp + (size_t)z * sB + (size_t)(n0 + pr) * ldb;
        mrow = rowM [(size_t)z * NPIX + n0 + pr];
        il   = rowIL[(size_t)z * NPIX + n0 + pr];
    }
    auto issueS = [&](int kc) {   // fp32 S tile -> smem staging (single buffer)
        if (kc >= nk) return;
        const uint32_t d = sf + pr * SF_ROW + jh * 64;
        const float* g = Srow + kc * 32 + jh * 16;
#pragma unroll
        for (int q = 0; q < 4; ++q) CPA(d + q * 16, g + q * 4);
    };
    auto convB = [&](int kc) {    // smem fp32 -> exp/split -> smem bf16 tiles
        const uint32_t s0 = sb + (kc & 1) * STAGE_SB;
        const float* Sf = (const float*)(smem + 2 * STAGE_SB + pr * SF_ROW + jh * 64);
        const uint32_t dH = s0 + 2 * TILE_SB + pr * RSB + jh * 32;
        const uint32_t dL = s0 + 3 * TILE_SB + pr * RSB + jh * 32;
#pragma unroll
        for (int v = 0; v < 2; ++v) {
            uint32_t hw[4], lw[4];
#pragma unroll
            for (int q = 0; q < 4; ++q) {
                float x0 = Sf[v * 8 + q * 2];
                float x1 = Sf[v * 8 + q * 2 + 1];
                float p0 = __expf(x0 - mrow) * il;
                float p1 = __expf(x1 - mrow) * il;
                bf16 h0, l0, h1, l1;
                split2(p0, h0, l0); split2(p1, h1, l1);
                __nv_bfloat162 hp(h0, h1), lp(l0, l1);
                hw[q] = *(uint32_t*)&hp; lw[q] = *(uint32_t*)&lp;
            }
            asm volatile("st.shared.v4.b32 [%0], {%1,%2,%3,%4};"
                :: "r"(dH + v * 16), "r"(hw[0]), "r"(hw[1]), "r"(hw[2]), "r"(hw[3]) : "memory");
            asm volatile("st.shared.v4.b32 [%0], {%1,%2,%3,%4};"
                :: "r"(dL + v * 16), "r"(lw[0]), "r"(lw[1]), "r"(lw[2]), "r"(lw[3]) : "memory");
        }
    };

    float acc[4][4][4];
#pragma unroll
    for (int i = 0; i < 4; ++i)
#pragma unroll
        for (int j = 0; j < 4; ++j)
#pragma unroll
            for (int q = 0; q < 4; ++q) acc[i][j][q] = 0.f;

    // Preamble: group0 = A(0) [+ S(0)], group1 = A(1)
    issueA(0); if (FUSEB) issueS(0); CPC();
    issueA(1); CPC();

    const int aRow = lane & 15;
    const int aKB  = (lane >> 4) * 16;
    const int bRow = lane & 7;
    const int bKB  = ((lane >> 3) & 1) * 16;

    for (int kc = 0; kc < nk; ++kc) {
        CPW(1);                      // A(kc) [+S(kc)] resident; A(kc+1) may fly
        if (FUSEB) convB(kc);
        __syncthreads();

        const uint32_t s0 = sb + (kc & 1) * STAGE_SB;
        const uint32_t aH = s0, aL = s0 + TILE_SB;
        const uint32_t bH = s0 + 2 * TILE_SB, bL = s0 + 3 * TILE_SB;
#pragma unroll
        for (int ks = 0; ks < 2; ++ks) {
            uint32_t Af[2][4][4];
#pragma unroll
            for (int i = 0; i < 4; ++i) {
                const uint32_t off = (uint32_t)(wm * 64 + i * 16 + aRow) * RSB + ks * 32 + aKB;
                ldsm4(Af[0][i], aH + off);
                ldsm4(Af[1][i], aL + off);
            }
#pragma unroll
            for (int j = 0; j < 4; ++j) {
                uint32_t Bf[2][2];
                const uint32_t off = (uint32_t)(wn * 32 + j * 8 + bRow) * RSB + ks * 32 + bKB;
                ldsm2(Bf[0], bH + off);
                ldsm2(Bf[1], bL + off);
#pragma unroll
                for (int i = 0; i < 4; ++i) {
                    mma_bf16(acc[i][j], Af[0][i], Bf[0]);   // hi*hi
                    mma_bf16(acc[i][j], Af[0][i], Bf[1]);   // hi*lo
                    mma_bf16(acc[i][j], Af[1][i], Bf[0]);   // lo*hi
                }
            }
        }
        __syncthreads();
        if (FUSEB) { issueS(kc + 1); CPC(); issueA(kc + 2); CPC(); }
        else       { issueA(kc + 2); CPC(); }
    }

    // ---- epilogue: stage D (+bias on m) through smem ----
    float* stg = (float*)smem;                   // [128][132]
    const int gid = lane >> 2, tig = lane & 3;
#pragma unroll
    for (int i = 0; i < 4; ++i) {
        const int ml = wm * 64 + i * 16 + gid;
        const float bv0 = bias ? bias[m0 + ml] : 0.f;
        const float bv8 = bias ? bias[m0 + ml + 8] : 0.f;
#pragma unroll
        for (int j = 0; j < 4; ++j) {
            const int nl = wn * 32 + j * 8 + tig * 2;
            stg[ml * 132 + nl]           = acc[i][j][0] + bv0;
            stg[ml * 132 + nl + 1]       = acc[i][j][1] + bv0;
            stg[(ml + 8) * 132 + nl]     = acc[i][j][2] + bv8;
            stg[(ml + 8) * 132 + nl + 1] = acc[i][j][3] + bv8;
        }
    }
    __syncthreads();

    const int row = tid >> 1, half = tid & 1;
    if (EPI == 0) {
        float* dst = outF + (size_t)z * sO + (size_t)(m0 + row) * ldo + n0 + half * 64;
        const float4* s4 = (const float4*)&stg[row * 132 + half * 64];
#pragma unroll
        for (int i = 0; i < 16; ++i) ((float4*)dst)[i] = s4[i];
    } else if (EPI == 1) {
        const size_t base = (size_t)z * sO + (size_t)(m0 + row) * ldo + n0 + half * 64;
#pragma unroll
        for (int v = 0; v < 8; ++v) {
            uint32_t hw[4], lw[4];
#pragma unroll
            for (int q = 0; q < 4; ++q) {
                float x0 = stg[row * 132 + half * 64 + v * 8 + q * 2];
                float x1 = stg[row * 132 + half * 64 + v * 8 + q * 2 + 1];
                bf16 h0, l0, h1, l1;
                split2(x0, h0, l0); split2(x1, h1, l1);
                __nv_bfloat162 hp(h0, h1), lp(l0, l1);
                hw[q] = *(uint32_t*)&hp; lw[q] = *(uint32_t*)&lp;
            }
            *(uint4*)(oH + base + v * 8) = make_uint4(hw[0], hw[1], hw[2], hw[3]);
            *(uint4*)(oL + base + v * 8) = make_uint4(lw[0], lw[1], lw[2], lw[3]);
        }
    } else {
        const int n = row, mh = half * 64;
        const size_t base = (size_t)z * sO + (size_t)(n0 + n) * ldo + m0 + mh;
#pragma unroll
        for (int v = 0; v < 8; ++v) {
            uint32_t hw[4], lw[4];
#pragma unroll
            for (int q = 0; q < 4; ++q) {
                float x0 = stg[(mh + v * 8 + q * 2) * 132 + n];
                float x1 = stg[(mh + v * 8 + q * 2 + 1) * 132 + n];
                bf16 h0, l0, h1, l1;
                split2(x0, h0, l0); split2(x1, h1, l1);
                __nv_bfloat162 hp(h0, h1), lp(l0, l1);
                hw[q] = *(uint32_t*)&hp; lw[q] = *(uint32_t*)&lp;
            }
            *(uint4*)(oH + base + v * 8) = make_uint4(hw[0], hw[1], hw[2], hw[3]);
            *(uint4*)(oL + base + v * 8) = make_uint4(lw[0], lw[1], lw[2], lw[3]);
        }
    }

    if (STATS) {
        float mx = -3.0e38f;
#pragma unroll
        for (int q = 0; q < 64; ++q) mx = fmaxf(mx, stg[row * 132 + half * 64 + q]);
        mx = fmaxf(mx, __shfl_xor_sync(0xffffffffu, mx, 1));
        float s = 0.f;
#pragma unroll
        for (int q = 0; q < 64; ++q) s += __expf(stg[row * 132 + half * 64 + q] - mx);
        s += __shfl_xor_sync(0xffffffffu, s, 1);
        if (half == 0) {
            size_t o = ((size_t)z * 32 + blockIdx.x) * NPIX + m0 + row;
            stM[o] = mx; stS[o] = s;
        }
    }
}

// ---------------------------------------------------------------------------
// Combine per-tile stats -> per-row (m, 1/l)
// ---------------------------------------------------------------------------
__global__ void __launch_bounds__(256)
combine_stats(const float* __restrict__ stM, const float* __restrict__ stS,
              float* __restrict__ rowM, float* __restrict__ rowIL)
{
    const int idx = blockIdx.x * 256 + threadIdx.x;
    if (idx >= BATCH * NPIX) return;
    const int z = idx >> 12, i = idx & (NPIX - 1);
    float m = -3.0e38f;
#pragma unroll 4
    for (int t = 0; t < 32; ++t)
        m = fmaxf(m, stM[((size_t)z * 32 + t) * NPIX + i]);
    float l = 0.f;
#pragma unroll 4
    for (int t = 0; t < 32; ++t) {
        size_t o = ((size_t)z * 32 + t) * NPIX + i;
        l += stS[o] * __expf(stM[o] - m);
    }
    rowM[idx] = m;
    rowIL[idx] = 1.0f / l;
}

// ---------------------------------------------------------------------------
// Both inputs: fp32 [b][c][p] -> bf16 hi/lo transposed [b][p][c]
// ---------------------------------------------------------------------------
__global__ void __launch_bounds__(256)
tsplit_both(const float* __restrict__ Fc, const float* __restrict__ Fs,
            bf16* __restrict__ ohc, bf16* __restrict__ olc,
            bf16* __restrict__ ohs, bf16* __restrict__ ols)
{
    __shared__ float t[32][33];
    const int zz = blockIdx.z;
    const int b = zz & 3;
    const float* X = (zz < 4) ? Fc : Fs;
    bf16* oh = (zz < 4) ? ohc : ohs;
    bf16* ol = (zz < 4) ? olc : ols;
    const int pb = blockIdx.x * 32, cb = blockIdx.y * 32;
    const float* src = X + (size_t)b * CDIM * NPIX;
#pragma unroll
    for (int j = 0; j < 4; ++j) {
        int c = cb + threadIdx.y + j * 8;
        t[threadIdx.y + j * 8][threadIdx.x] = src[(size_t)c * NPIX + pb + threadIdx.x];
    }
    __syncthreads();
#pragma unroll
    for (int j = 0; j < 4; ++j) {
        int p = pb + threadIdx.y + j * 8;
        float v = t[threadIdx.x][threadIdx.y + j * 8];
        size_t o = (size_t)b * NPIX * CDIM + (size_t)p * CDIM + cb + threadIdx.x;
        bf16 h, l; split2(v, h, l);
        oh[o] = h; ol[o] = l;
    }
}

__global__ void __launch_bounds__(256)
wsplit_all(const float* __restrict__ w0, const float* __restrict__ w1,
           const float* __restrict__ w2, const float* __restrict__ w3,
           bf16* __restrict__ h0, bf16* __restrict__ l0,
           bf16* __restrict__ h1, bf16* __restrict__ l1,
           bf16* __restrict__ h2, bf16* __restrict__ l2,
           bf16* __restrict__ h3, bf16* __restrict__ l3)
{
    const float* w = (blockIdx.y == 0) ? w0 : (blockIdx.y == 1) ? w1 : (blockIdx.y == 2) ? w2 : w3;
    bf16* hh = (blockIdx.y == 0) ? h0 : (blockIdx.y == 1) ? h1 : (blockIdx.y == 2) ? h2 : h3;
    bf16* ll = (blockIdx.y == 0) ? l0 : (blockIdx.y == 1) ? l1 : (blockIdx.y == 2) ? l2 : l3;
    int i = blockIdx.x * 256 + threadIdx.x;
    if (i < CDIM * CDIM) { bf16 a, b; split2(w[i], a, b); hh[i] = a; ll[i] = b; }
}

// ---------------------------------------------------------------------------
// Launch. wsplit(1), tsplit(2), G1(3), G2(4), G4+stats(5: ncu), G3(6),
//         combine(7), G5 fused(8), G6(9)
// ---------------------------------------------------------------------------
extern "C" void kernel_launch(void* const* d_in, const int* in_sizes, int n_in,
                              void* d_out, int out_size)
{
    const float* F_c = (const float*)d_in[0];
    const float* F_s = (const float*)d_in[1];
    const float* w_f = (const float*)d_in[2];
    const float* b_f = (const float*)d_in[3];
    const float* w_g = (const float*)d_in[4];
    const float* b_g = (const float*)d_in[5];
    const float* w_h = (const float*)d_in[6];
    const float* b_h = (const float*)d_in[7];
    const float* w_o = (const float*)d_in[8];
    const float* b_o = (const float*)d_in[9];
    float* out = (float*)d_out;

    bf16 *FcTh, *FcTl, *FsTh, *FsTl, *wfh, *wfl, *wgh, *wgl, *whh, *whl, *woh, *wol;
    bf16 *Fqh, *Fql, *Gh, *Gl, *Hvh, *Hvl, *Rh, *Rl;
    float *S, *stM, *stS, *rowM, *rowIL;
    cudaGetSymbolAddress((void**)&FcTh, g_FcT_h); cudaGetSymbolAddress((void**)&FcTl, g_FcT_l);
    cudaGetSymbolAddress((void**)&FsTh, g_FsT_h); cudaGetSymbolAddress((void**)&FsTl, g_FsT_l);
    cudaGetSymbolAddress((void**)&wfh, g_wf_h);   cudaGetSymbolAddress((void**)&wfl, g_wf_l);
    cudaGetSymbolAddress((void**)&wgh, g_wg_h);   cudaGetSymbolAddress((void**)&wgl, g_wg_l);
    cudaGetSymbolAddress((void**)&whh, g_wh_h);   cudaGetSymbolAddress((void**)&whl, g_wh_l);
    cudaGetSymbolAddress((void**)&woh, g_wo_h);   cudaGetSymbolAddress((void**)&wol, g_wo_l);
    cudaGetSymbolAddress((void**)&Fqh, g_Fq_h);   cudaGetSymbolAddress((void**)&Fql, g_Fq_l);
    cudaGetSymbolAddress((void**)&Gh,  g_G_h);    cudaGetSymbolAddress((void**)&Gl,  g_G_l);
    cudaGetSymbolAddress((void**)&Hvh, g_Hv_h);   cudaGetSymbolAddress((void**)&Hvl, g_Hv_l);
    cudaGetSymbolAddress((void**)&Rh,  g_R_h);    cudaGetSymbolAddress((void**)&Rl,  g_R_l);
    cudaGetSymbolAddress((void**)&S,   g_S);
    cudaGetSymbolAddress((void**)&stM, g_stM);    cudaGetSymbolAddress((void**)&stS, g_stS);
    cudaGetSymbolAddress((void**)&rowM, g_rowM);  cudaGetSymbolAddress((void**)&rowIL, g_rowIL);

    cudaFuncSetAttribute(mma_gemm<2,false,false>, cudaFuncAttributeMaxDynamicSharedMemorySize, DSMEM);
    cudaFuncSetAttribute(mma_gemm<1,false,false>, cudaFuncAttributeMaxDynamicSharedMemorySize, DSMEM);
    cudaFuncSetAttribute(mma_gemm<0,true ,false>, cudaFuncAttributeMaxDynamicSharedMemorySize, DSMEM);
    cudaFuncSetAttribute(mma_gemm<2,false,true >, cudaFuncAttributeMaxDynamicSharedMemorySize, DSMEM_F);
    cudaFuncSetAttribute(mma_gemm<0,false,false>, cudaFuncAttributeMaxDynamicSharedMemorySize, DSMEM);

    const long long cn = (long long)NPIX * CDIM;
    const long long nn = (long long)NPIX * NPIX;

    dim3 gConv(NPIX / 128, CDIM / 128, BATCH);   // 32 x 2 x 4
    dim3 gS(NPIX / 128, NPIX / 128, BATCH);      // 32 x 32 x 4

    wsplit_all<<<dim3(256, 4), 256>>>(w_f, w_g, w_h, w_o,
        wfh, wfl, wgh, wgl, whh, whl, woh, wol);
    tsplit_both<<<dim3(128, 8, 8), dim3(32, 8)>>>(F_c, F_s, FcTh, FcTl, FsTh, FsTl);
    // G1
    mma_gemm<2,false,false><<<gConv, 256, DSMEM>>>(wfh, wfl, FcTh, FcTl,
        CDIM, CDIM, CDIM, CDIM, 0, cn, cn, b_f, nullptr, Fqh, Fql,
        nullptr, nullptr, nullptr, nullptr, nullptr);
    // G2
    mma_gemm<2,false,false><<<gConv, 256, DSMEM>>>(wgh, wgl, FsTh, FsTl,
        CDIM, CDIM, CDIM, CDIM, 0, cn, cn, b_g, nullptr, Gh, Gl,
        nullptr, nullptr, nullptr, nullptr, nullptr);
    // G4 + stats — ncu target
    mma_gemm<0,true,false><<<gS, 256, DSMEM>>>(Fqh, Fql, Gh, Gl,
        CDIM, CDIM, CDIM, NPIX, cn, cn, nn, nullptr, S, nullptr, nullptr,
        nullptr, nullptr, nullptr, stM, stS);
    // G3
    mma_gemm<1,false,false><<<gConv, 256, DSMEM>>>(whh, whl, FsTh, FsTl,
        CDIM, CDIM, CDIM, NPIX, 0, cn, cn, b_h, nullptr, Hvh, Hvl,
        nullptr, nullptr, nullptr, nullptr, nullptr);
    // stats fold
    combine_stats<<<(BATCH * NPIX + 255) / 256, 256>>>(stM, stS, rowM, rowIL);
    // G5 fused (P from fp32 S via smem staging)
    mma_gemm<2,false,true><<<gConv, 256, DSMEM_F>>>(Hvh, Hvl, nullptr, nullptr,
        NPIX, NPIX, NPIX, CDIM, cn, nn, cn, nullptr, nullptr, Rh, Rl,
        S, rowM, rowIL, nullptr, nullptr);
    // G6
    mma_gemm<0,false,false><<<gConv, 256, DSMEM>>>(woh, wol, Rh, Rl,
        CDIM, CDIM, CDIM, NPIX, 0, cn, cn, b_o, out, nullptr, nullptr,
        nullptr, nullptr, nullptr, nullptr, nullptr);
}